// round 1
// baseline (speedup 1.0000x reference)
#include <cuda_runtime.h>
#include <cstddef>

// ---------------- problem constants ----------------
#define N_NODES 50000
#define DIM     128
#define NEG_SLOPE 0.2f

// ---------------- scratch (device globals; no allocs allowed) ----------------
__device__ float g_deg[N_NODES];
__device__ float g_hq [(size_t)N_NODES * DIM];
__device__ float g_hk [(size_t)N_NODES * DIM];
__device__ float g_agg[(size_t)N_NODES * DIM];
__device__ float g_h1 [(size_t)N_NODES * DIM];
__device__ float g_h2 [(size_t)N_NODES * DIM];

__device__ __forceinline__ float leakyf(float x) {
    return x >= 0.f ? x : NEG_SLOPE * x;
}

// ---------------- zero fill (float4 granularity) ----------------
__global__ void zero_f4(float* __restrict__ p, long n4) {
    long i = (long)blockIdx.x * blockDim.x + threadIdx.x;
    if (i < n4) ((float4*)p)[i] = make_float4(0.f, 0.f, 0.f, 0.f);
}

// ---------------- in-degree ----------------
__global__ void deg_kernel(const int* __restrict__ dst, int E, float* __restrict__ deg) {
    int i = blockIdx.x * blockDim.x + threadIdx.x;
    if (i < E) atomicAdd(&deg[dst[i]], 1.0f);
}

// ---------------- edge message + scatter-add ----------------
// one warp per edge; each lane handles 4 contiguous floats (float4)
__global__ void edge_kernel(const int* __restrict__ src, const int* __restrict__ dst,
                            const float* __restrict__ hq, const float* __restrict__ hk,
                            float* __restrict__ agg, int E) {
    int gt   = blockIdx.x * blockDim.x + threadIdx.x;
    int e    = gt >> 5;
    int lane = threadIdx.x & 31;
    if (e >= E) return;
    int s = __ldg(&src[e]);
    int d = __ldg(&dst[e]);
    float4 q = __ldg(((const float4*)hq) + (size_t)d * (DIM / 4) + lane);
    float4 k = __ldg(((const float4*)hk) + (size_t)s * (DIM / 4) + lane);
    float4 m;
    m.x = leakyf(q.x + k.x);
    m.y = leakyf(q.y + k.y);
    m.z = leakyf(q.z + k.z);
    m.w = leakyf(q.w + k.w);
    float* p = agg + (size_t)d * DIM + lane * 4;
    asm volatile("red.global.add.v4.f32 [%0], {%1, %2, %3, %4};"
                 :: "l"(p), "f"(m.x), "f"(m.y), "f"(m.z), "f"(m.w)
                 : "memory");
}

// ---------------- fp32 GEMM: C[N,128] = act( scale(A) @ W[128,128] + b ) ----------------
// BM=64 rows/block, 256 threads, each thread computes 4 rows x 8 cols.
// W fully resident in smem [k][n] (64KB), A tile transposed in smem [k][row] (32KB).
// deg != nullptr  -> A row r is scaled by 1/max(deg[r],1)  (mean aggregation)
// doLeaky         -> leaky ReLU on output
// doAcc           -> C += result   (else C = result)
__global__ void __launch_bounds__(256, 2)
gemm128(const float* __restrict__ A, const float* __restrict__ W,
        const float* __restrict__ b, float* __restrict__ C,
        const float* __restrict__ deg, int N, int doLeaky, int doAcc) {
    extern __shared__ float sm[];
    float* Ws = sm;                 // [128][128]
    float* As = sm + 128 * 128;     // [128][64] (k-major, transposed)

    int tid  = threadIdx.x;
    int row0 = blockIdx.x * 64;

    // load W (16384 floats = 4096 float4)
    for (int i = tid; i < 128 * 32; i += 256) {
        ((float4*)Ws)[i] = __ldg(((const float4*)W) + i);
    }
    // load A tile transposed, with optional row scale
    for (int i = tid; i < 64 * 32; i += 256) {
        int r  = i >> 5;       // 0..63
        int kq = i & 31;       // float4 index along k
        int g  = row0 + r;
        float4 v = make_float4(0.f, 0.f, 0.f, 0.f);
        float sc = 1.f;
        if (g < N) {
            v = __ldg(((const float4*)(A + (size_t)g * DIM)) + kq);
            if (deg) {
                float dv = deg[g];
                if (dv > 1.f) sc = 1.f / dv;
            }
        }
        As[(kq * 4 + 0) * 64 + r] = v.x * sc;
        As[(kq * 4 + 1) * 64 + r] = v.y * sc;
        As[(kq * 4 + 2) * 64 + r] = v.z * sc;
        As[(kq * 4 + 3) * 64 + r] = v.w * sc;
    }
    __syncthreads();

    int ty = tid >> 4;      // 0..15
    int tx = tid & 15;      // 0..15
    int r0 = ty * 4;
    int c0 = tx * 8;

    float acc[4][8];
#pragma unroll
    for (int r = 0; r < 4; r++)
#pragma unroll
        for (int c = 0; c < 8; c++) acc[r][c] = 0.f;

#pragma unroll 4
    for (int k = 0; k < 128; k++) {
        float4 a  = *(const float4*)&As[k * 64 + r0];
        float4 w0 = *(const float4*)&Ws[k * 128 + c0];
        float4 w1 = *(const float4*)&Ws[k * 128 + c0 + 4];
        float av[4] = {a.x, a.y, a.z, a.w};
        float wv[8] = {w0.x, w0.y, w0.z, w0.w, w1.x, w1.y, w1.z, w1.w};
#pragma unroll
        for (int r = 0; r < 4; r++)
#pragma unroll
            for (int c = 0; c < 8; c++)
                acc[r][c] = fmaf(av[r], wv[c], acc[r][c]);
    }

    float bias[8];
#pragma unroll
    for (int c = 0; c < 8; c++) bias[c] = __ldg(&b[c0 + c]);

#pragma unroll
    for (int r = 0; r < 4; r++) {
        int g = row0 + r0 + r;
        if (g >= N) continue;
        float* cp = C + (size_t)g * DIM + c0;
#pragma unroll
        for (int c = 0; c < 8; c++) {
            float v = acc[r][c] + bias[c];
            if (doLeaky) v = leakyf(v);
            if (doAcc) cp[c] += v;
            else       cp[c]  = v;
        }
    }
}

// ---------------- launch ----------------
extern "C" void kernel_launch(void* const* d_in, const int* in_sizes, int n_in,
                              void* d_out, int out_size) {
    const float* feats = (const float*)d_in[0];
    const float* Wq    = (const float*)d_in[1];
    const float* bq    = (const float*)d_in[2];
    const float* Wk    = (const float*)d_in[3];
    const float* bk    = (const float*)d_in[4];
    const float* Wr    = (const float*)d_in[5];
    const float* br    = (const float*)d_in[6];
    const float* Wro   = (const float*)d_in[7];
    const float* bro   = (const float*)d_in[8];
    const int*   src   = (const int*)d_in[9];
    const int*   dst   = (const int*)d_in[10];

    int N = in_sizes[0] / DIM;   // 50000
    int E = in_sizes[9];         // 800000
    float* out = (float*)d_out;

    float *deg, *hq, *hk, *agg, *h1, *h2;
    cudaGetSymbolAddress((void**)&deg, g_deg);
    cudaGetSymbolAddress((void**)&hq,  g_hq);
    cudaGetSymbolAddress((void**)&hk,  g_hk);
    cudaGetSymbolAddress((void**)&agg, g_agg);
    cudaGetSymbolAddress((void**)&h1,  g_h1);
    cudaGetSymbolAddress((void**)&h2,  g_h2);

    const int SMEM = (128 * 128 + 128 * 64) * (int)sizeof(float);  // 96KB
    cudaFuncSetAttribute(gemm128, cudaFuncAttributeMaxDynamicSharedMemorySize, SMEM);

    dim3 gB((N + 63) / 64);

    // in-degree
    zero_f4<<<(N / 4 + 255) / 256, 256>>>(deg, N / 4);
    deg_kernel<<<(E + 255) / 256, 256>>>(dst, E, deg);

    const float* h = feats;
    float* houts[2] = {h1, h2};
    for (int L = 0; L < 2; L++) {
        const float* WqL = Wq + (size_t)L * DIM * DIM;
        const float* WkL = Wk + (size_t)L * DIM * DIM;
        const float* WrL = Wr + (size_t)L * DIM * DIM;
        gemm128<<<gB, 256, SMEM>>>(h, WqL, bq + L * DIM, hq, nullptr, N, 0, 0);
        gemm128<<<gB, 256, SMEM>>>(h, WkL, bk + L * DIM, hk, nullptr, N, 0, 0);
        long n4 = (long)N * (DIM / 4);
        zero_f4<<<(int)((n4 + 255) / 256), 256>>>(agg, n4);
        long ethreads = (long)E * 32;
        edge_kernel<<<(int)((ethreads + 255) / 256), 256>>>(src, dst, hq, hk, agg, E);
        gemm128<<<gB, 256, SMEM>>>(agg, WrL, br + L * DIM, houts[L], deg, N, 1, 0);
        h = houts[L];
    }

    // jumping-knowledge readout
    gemm128<<<gB, 256, SMEM>>>(feats, Wro + 0 * DIM * DIM, bro + 0 * DIM, out, nullptr, N, 0, 0);
    gemm128<<<gB, 256, SMEM>>>(h1,    Wro + 1 * DIM * DIM, bro + 1 * DIM, out, nullptr, N, 0, 1);
    gemm128<<<gB, 256, SMEM>>>(h2,    Wro + 2 * DIM * DIM, bro + 2 * DIM, out, nullptr, N, 0, 1);
}

// round 3
// speedup vs baseline: 2.2107x; 2.2107x over previous
#include <cuda_runtime.h>
#include <cuda_bf16.h>
#include <cstdint>
#include <cstddef>

// ---------------- problem constants ----------------
#define N_NODES 50000
#define DIM     128
#define NEG_SLOPE 0.2f

// ---- SMEM layout: 128-row tiles, bf16, 272-byte padded rows (conflict-free) ----
#define ROWB     272
#define TILE_SZ  (128 * ROWB)        // 34816
#define AH_OFF   0
#define AL_OFF   TILE_SZ
#define BH_OFF   (2 * TILE_SZ)
#define BL_OFF   (3 * TILE_SZ)
#define SMEM_TOTAL (4 * TILE_SZ)     // 139264

// ---------------- scratch (device globals; no allocs allowed) ----------------
__device__ float g_deg[N_NODES];
__device__ float g_hq [(size_t)N_NODES * DIM];
__device__ float g_hk [(size_t)N_NODES * DIM];
__device__ float g_agg[(size_t)N_NODES * DIM];
__device__ float g_h1 [(size_t)N_NODES * DIM];
__device__ float g_h2 [(size_t)N_NODES * DIM];
// 9 matrices x (hi 8192 u32 + lo 8192 u32)
__device__ unsigned g_wpack[9 * 16384];

__device__ __forceinline__ float leakyf(float x) { return x >= 0.f ? x : NEG_SLOPE * x; }

static __device__ __forceinline__ unsigned pack_bf2(float a, float b) {
    __nv_bfloat162 h = __floats2bfloat162_rn(a, b);
    return *(unsigned*)&h;
}

// ---------------- zero fill ----------------
__global__ void zero_f4(float* __restrict__ p, long n4) {
    long i = (long)blockIdx.x * blockDim.x + threadIdx.x;
    if (i < n4) ((float4*)p)[i] = make_float4(0.f, 0.f, 0.f, 0.f);
}

// ---------------- in-degree ----------------
__global__ void deg_kernel(const int* __restrict__ dst, int E, float* __restrict__ deg) {
    int i = blockIdx.x * blockDim.x + threadIdx.x;
    if (i < E) atomicAdd(&deg[dst[i]], 1.0f);
}

// ---------------- edge message + scatter-add (warp per edge, red.v4) ----------------
__global__ void edge_kernel(const int* __restrict__ src, const int* __restrict__ dst,
                            const float* __restrict__ hq, const float* __restrict__ hk,
                            float* __restrict__ agg, int E) {
    int gt   = blockIdx.x * blockDim.x + threadIdx.x;
    int e    = gt >> 5;
    int lane = threadIdx.x & 31;
    if (e >= E) return;
    int s = __ldg(&src[e]);
    int d = __ldg(&dst[e]);
    float4 q = __ldg(((const float4*)hq) + (size_t)d * (DIM / 4) + lane);
    float4 k = __ldg(((const float4*)hk) + (size_t)s * (DIM / 4) + lane);
    float4 m;
    m.x = leakyf(q.x + k.x);
    m.y = leakyf(q.y + k.y);
    m.z = leakyf(q.z + k.z);
    m.w = leakyf(q.w + k.w);
    float* p = agg + (size_t)d * DIM + lane * 4;
    asm volatile("red.global.add.v4.f32 [%0], {%1, %2, %3, %4};"
                 :: "l"(p), "f"(m.x), "f"(m.y), "f"(m.z), "f"(m.w) : "memory");
}

// ---------------- pack weights: bf16 hi/lo images, layout [n][k] (transposed) ----------------
__global__ void pack_w(const float* __restrict__ Wq, const float* __restrict__ Wk,
                       const float* __restrict__ Wr, const float* __restrict__ Wro) {
    int mat = blockIdx.x;  // 0..8
    const float* W;
    switch (mat) {
        case 0: W = Wq;         break;
        case 1: W = Wk;         break;
        case 2: W = Wr;         break;
        case 3: W = Wq + 16384; break;
        case 4: W = Wk + 16384; break;
        case 5: W = Wr + 16384; break;
        default: W = Wro + (mat - 6) * 16384; break;
    }
    unsigned short* hi = (unsigned short*)(g_wpack + (size_t)mat * 16384);
    unsigned short* lo = (unsigned short*)(g_wpack + (size_t)mat * 16384 + 8192);
    int n = threadIdx.x;  // 0..127
    for (int k = 0; k < 128; k++) {
        float w = __ldg(&W[k * 128 + n]);
        __nv_bfloat16 h = __float2bfloat16(w);
        float l = w - __bfloat162float(h);
        __nv_bfloat16 e = __float2bfloat16(l);
        hi[n * 128 + k] = __bfloat16_as_ushort(h);
        lo[n * 128 + k] = __bfloat16_as_ushort(e);
    }
}

// ---------------- GEMM building blocks (256 threads/CTA) ----------------
// convert fp32 A tile -> bf16 hi/lo in SMEM, optional 1/max(deg,1) row scale
static __device__ __forceinline__ void conv_A(char* sm, const float* __restrict__ A,
                                              int row0, int N, const float* __restrict__ deg) {
#pragma unroll
    for (int it = 0; it < 16; it++) {
        int idx = it * 256 + threadIdx.x;   // 0..4095
        int r  = idx >> 5;
        int c4 = idx & 31;
        int gidx = row0 + r;
        int gc = gidx < N ? gidx : N - 1;
        float4 v = __ldg(((const float4*)(A + (size_t)gc * 128)) + c4);
        if (deg) {
            float dv = deg[gc];
            if (dv > 1.f) {
                float sc = 1.f / dv;
                v.x *= sc; v.y *= sc; v.z *= sc; v.w *= sc;
            }
        }
        float hx = __bfloat162float(__float2bfloat16(v.x));
        float hy = __bfloat162float(__float2bfloat16(v.y));
        float hz = __bfloat162float(__float2bfloat16(v.z));
        float hw = __bfloat162float(__float2bfloat16(v.w));
        uint2 hiP = make_uint2(pack_bf2(v.x, v.y), pack_bf2(v.z, v.w));
        uint2 loP = make_uint2(pack_bf2(v.x - hx, v.y - hy), pack_bf2(v.z - hz, v.w - hw));
        *(uint2*)(sm + AH_OFF + r * ROWB + c4 * 8) = hiP;
        *(uint2*)(sm + AL_OFF + r * ROWB + c4 * 8) = loP;
    }
}

// copy packed weight hi/lo images into padded SMEM
static __device__ __forceinline__ void copy_B(char* sm, int widx) {
    const uint4* src = (const uint4*)(g_wpack + (size_t)widx * 16384);
#pragma unroll
    for (int it = 0; it < 8; it++) {
        int i = it * 256 + threadIdx.x;   // 0..2047
        int r = i >> 4, c = i & 15;
        *(uint4*)(sm + BH_OFF + r * ROWB + c * 16) = __ldg(src + i);
        *(uint4*)(sm + BL_OFF + r * ROWB + c * 16) = __ldg(src + 2048 + i);
    }
}

static __device__ __forceinline__ void mma_bf16(float* c, uint32_t a0, uint32_t a1,
                                                uint32_t a2, uint32_t a3,
                                                uint32_t b0, uint32_t b1) {
    asm volatile("mma.sync.aligned.m16n8k16.row.col.f32.bf16.bf16.f32 "
                 "{%0,%1,%2,%3}, {%4,%5,%6,%7}, {%8,%9}, {%0,%1,%2,%3};"
                 : "+f"(c[0]), "+f"(c[1]), "+f"(c[2]), "+f"(c[3])
                 : "r"(a0), "r"(a1), "r"(a2), "r"(a3), "r"(b0), "r"(b1));
}

// warp tile 32(M) x 64(N); 3 split segments: Ah*Wh + Al*Wh + Ah*Wl
static __device__ __forceinline__ void run_mma(float acc[2][8][4], const char* sm,
                                               int mbase, int nbase, int g, int t) {
#pragma unroll
    for (int s = 0; s < 3; s++) {
        const char* Ab = sm + (s == 1 ? AL_OFF : AH_OFF) + (mbase + g) * ROWB + t * 4;
        const char* Bb = sm + (s == 2 ? BL_OFF : BH_OFF) + (nbase + g) * ROWB + t * 4;
#pragma unroll
        for (int ks = 0; ks < 8; ks++) {
            int kb = ks * 32;
            uint32_t b[8][2];
#pragma unroll
            for (int nf = 0; nf < 8; nf++) {
                b[nf][0] = *(const uint32_t*)(Bb + nf * (8 * ROWB) + kb);
                b[nf][1] = *(const uint32_t*)(Bb + nf * (8 * ROWB) + kb + 16);
            }
#pragma unroll
            for (int mf = 0; mf < 2; mf++) {
                const char* ap = Ab + mf * (16 * ROWB) + kb;
                uint32_t a0 = *(const uint32_t*)ap;
                uint32_t a1 = *(const uint32_t*)(ap + 8 * ROWB);
                uint32_t a2 = *(const uint32_t*)(ap + 16);
                uint32_t a3 = *(const uint32_t*)(ap + 8 * ROWB + 16);
#pragma unroll
                for (int nf = 0; nf < 8; nf++)
                    mma_bf16(acc[mf][nf], a0, a1, a2, a3, b[nf][0], b[nf][1]);
            }
        }
    }
}

static __device__ __forceinline__ void zero_acc(float acc[2][8][4]) {
#pragma unroll
    for (int mf = 0; mf < 2; mf++)
#pragma unroll
        for (int nf = 0; nf < 8; nf++)
#pragma unroll
            for (int i = 0; i < 4; i++) acc[mf][nf][i] = 0.f;
}

static __device__ __forceinline__ void epi(float acc[2][8][4], float* __restrict__ out,
                                           int row0, int mbase, int nbase, int g, int t,
                                           const float* b0, const float* b1, const float* b2,
                                           int N, int doLeaky) {
    float bias[8][2];
#pragma unroll
    for (int nf = 0; nf < 8; nf++) {
#pragma unroll
        for (int i = 0; i < 2; i++) {
            int col = nbase + nf * 8 + t * 2 + i;
            float bb = __ldg(&b0[col]);
            if (b1) bb += __ldg(&b1[col]);
            if (b2) bb += __ldg(&b2[col]);
            bias[nf][i] = bb;
        }
    }
#pragma unroll
    for (int mf = 0; mf < 2; mf++) {
#pragma unroll
        for (int half = 0; half < 2; half++) {
            int row = row0 + mbase + mf * 16 + g + half * 8;
            if (row < N) {
                float* op = out + (size_t)row * 128;
#pragma unroll
                for (int nf = 0; nf < 8; nf++) {
                    float x = acc[mf][nf][half * 2 + 0] + bias[nf][0];
                    float y = acc[mf][nf][half * 2 + 1] + bias[nf][1];
                    if (doLeaky) { x = leakyf(x); y = leakyf(y); }
                    *(float2*)(op + nbase + nf * 8 + t * 2) = make_float2(x, y);
                }
            }
        }
    }
}

// ---------------- fused Q/K GEMM: hq = A@Wq + bq ; hk = A@Wk + bk ----------------
__global__ void __launch_bounds__(256, 1)
gemm_qk(const float* __restrict__ A, int wq, int wk,
        const float* __restrict__ bq, const float* __restrict__ bk,
        float* __restrict__ hq, float* __restrict__ hk, int N) {
    extern __shared__ char sm[];
    int tid = threadIdx.x, w = tid >> 5, lane = tid & 31;
    int g = lane >> 2, t = lane & 3;
    int mbase = (w >> 1) * 32, nbase = (w & 1) * 64;
    int row0 = blockIdx.x * 128;

    conv_A(sm, A, row0, N, nullptr);
    copy_B(sm, wq);
    __syncthreads();

    float acc[2][8][4];
    zero_acc(acc);
    run_mma(acc, sm, mbase, nbase, g, t);
    epi(acc, hq, row0, mbase, nbase, g, t, bq, nullptr, nullptr, N, 0);

    __syncthreads();
    copy_B(sm, wk);
    __syncthreads();

    zero_acc(acc);
    run_mma(acc, sm, mbase, nbase, g, t);
    epi(acc, hk, row0, mbase, nbase, g, t, bk, nullptr, nullptr, N, 0);
}

// ---------------- multi-stage accumulating GEMM ----------------
// out = act( sum_s A_s @ W_s + sum_s b_s ); deg-scale applied to A_0 rows if deg != null
__global__ void __launch_bounds__(256, 1)
gemm_multi(const float* __restrict__ a0, const float* __restrict__ a1, const float* __restrict__ a2,
           int w0, int w1, int w2,
           const float* __restrict__ b0, const float* __restrict__ b1, const float* __restrict__ b2,
           const float* __restrict__ deg, float* __restrict__ out, int N, int nst, int doLeaky) {
    extern __shared__ char sm[];
    int tid = threadIdx.x, w = tid >> 5, lane = tid & 31;
    int g = lane >> 2, t = lane & 3;
    int mbase = (w >> 1) * 32, nbase = (w & 1) * 64;
    int row0 = blockIdx.x * 128;

    const float* As[3] = {a0, a1, a2};
    int ws[3] = {w0, w1, w2};

    float acc[2][8][4];
    zero_acc(acc);

    for (int s = 0; s < nst; s++) {
        if (s) __syncthreads();
        conv_A(sm, As[s], row0, N, (s == 0) ? deg : nullptr);
        copy_B(sm, ws[s]);
        __syncthreads();
        run_mma(acc, sm, mbase, nbase, g, t);
    }

    epi(acc, out, row0, mbase, nbase, g, t, b0, b1, b2, N, doLeaky);
}

// ---------------- launch ----------------
extern "C" void kernel_launch(void* const* d_in, const int* in_sizes, int n_in,
                              void* d_out, int out_size) {
    const float* feats = (const float*)d_in[0];
    const float* Wq    = (const float*)d_in[1];
    const float* bq    = (const float*)d_in[2];
    const float* Wk    = (const float*)d_in[3];
    const float* bk    = (const float*)d_in[4];
    const float* Wr    = (const float*)d_in[5];
    const float* br    = (const float*)d_in[6];
    const float* Wro   = (const float*)d_in[7];
    const float* bro   = (const float*)d_in[8];
    const int*   src   = (const int*)d_in[9];
    const int*   dst   = (const int*)d_in[10];

    int N = in_sizes[0] / DIM;   // 50000
    int E = in_sizes[9];         // 800000
    float* out = (float*)d_out;

    float *deg, *hq, *hk, *agg, *h1, *h2;
    cudaGetSymbolAddress((void**)&deg, g_deg);
    cudaGetSymbolAddress((void**)&hq,  g_hq);
    cudaGetSymbolAddress((void**)&hk,  g_hk);
    cudaGetSymbolAddress((void**)&agg, g_agg);
    cudaGetSymbolAddress((void**)&h1,  g_h1);
    cudaGetSymbolAddress((void**)&h2,  g_h2);

    cudaFuncSetAttribute(gemm_qk,    cudaFuncAttributeMaxDynamicSharedMemorySize, SMEM_TOTAL);
    cudaFuncSetAttribute(gemm_multi, cudaFuncAttributeMaxDynamicSharedMemorySize, SMEM_TOTAL);

    int gM = (N + 127) / 128;    // 391
    long n4 = (long)N * (DIM / 4);
    long ethreads = (long)E * 32;

    // pack all 9 weight matrices into bf16 hi/lo [n][k] images
    pack_w<<<9, 128>>>(Wq, Wk, Wr, Wro);

    // in-degree
    zero_f4<<<(N / 4 + 255) / 256, 256>>>(deg, N / 4);
    deg_kernel<<<(E + 255) / 256, 256>>>(dst, E, deg);

    // ---- layer 0 ----
    gemm_qk<<<gM, 256, SMEM_TOTAL>>>(feats, 0, 1, bq, bk, hq, hk, N);
    zero_f4<<<(int)((n4 + 255) / 256), 256>>>(agg, n4);
    edge_kernel<<<(int)((ethreads + 255) / 256), 256>>>(src, dst, hq, hk, agg, E);
    gemm_multi<<<gM, 256, SMEM_TOTAL>>>(agg, nullptr, nullptr, 2, -1, -1,
                                        br, nullptr, nullptr, deg, h1, N, 1, 1);

    // ---- layer 1 ----
    gemm_qk<<<gM, 256, SMEM_TOTAL>>>(h1, 3, 4, bq + 128, bk + 128, hq, hk, N);
    zero_f4<<<(int)((n4 + 255) / 256), 256>>>(agg, n4);
    edge_kernel<<<(int)((ethreads + 255) / 256), 256>>>(src, dst, hq, hk, agg, E);
    gemm_multi<<<gM, 256, SMEM_TOTAL>>>(agg, nullptr, nullptr, 5, -1, -1,
                                        br + 128, nullptr, nullptr, deg, h2, N, 1, 1);

    // ---- jumping-knowledge readout (3 stages accumulated in registers) ----
    gemm_multi<<<gM, 256, SMEM_TOTAL>>>(feats, h1, h2, 6, 7, 8,
                                        bro, bro + 128, bro + 256, nullptr, out, N, 3, 0);
}

// round 4
// speedup vs baseline: 2.9323x; 1.3265x over previous
#include <cuda_runtime.h>
#include <cuda_bf16.h>
#include <cstdint>
#include <cstddef>

// ---------------- problem constants ----------------
#define N_NODES 50000
#define N_EDGES 800000
#define DIM     128
#define NEG_SLOPE 0.2f

// ---- SMEM layout: 128-row tiles, bf16, 272-byte padded rows (conflict-free) ----
#define ROWB     272
#define TILE_SZ  (128 * ROWB)        // 34816
#define AH_OFF   0
#define AL_OFF   TILE_SZ
#define BH_OFF   (2 * TILE_SZ)
#define BL_OFF   (3 * TILE_SZ)
#define SMEM_TOTAL (4 * TILE_SZ)     // 139264

// ---------------- scratch (device globals; no allocs allowed) ----------------
__device__ float g_hq [(size_t)N_NODES * DIM];
__device__ float g_hk [(size_t)N_NODES * DIM];
__device__ float g_agg[(size_t)N_NODES * DIM];
__device__ float g_h1 [(size_t)N_NODES * DIM];
__device__ float g_h2 [(size_t)N_NODES * DIM];
__device__ unsigned g_wpack[9 * 16384];     // 9 x (hi 8192 u32 + lo 8192 u32)
__device__ int g_cnt[N_NODES];
__device__ int g_off[N_NODES + 1];
__device__ int g_cur[N_NODES];
__device__ int g_csrc[N_EDGES];

__device__ __forceinline__ float leakyf(float x) { return x >= 0.f ? x : NEG_SLOPE * x; }

static __device__ __forceinline__ unsigned pack_bf2(float a, float b) {
    __nv_bfloat162 h = __floats2bfloat162_rn(a, b);
    return *(unsigned*)&h;
}

// ---------------- CSR build ----------------
__global__ void zero_int(int* __restrict__ p, int n) {
    int i = blockIdx.x * blockDim.x + threadIdx.x;
    if (i < n) p[i] = 0;
}

__global__ void cnt_kernel(const int* __restrict__ dst, int E, int* __restrict__ cnt) {
    int i = blockIdx.x * blockDim.x + threadIdx.x;
    if (i < E) atomicAdd(&cnt[dst[i]], 1);
}

// single-block exclusive scan (Kogge-Stone per 1024-chunk + running carry)
__global__ void scan_kernel(const int* __restrict__ cnt, int* __restrict__ off,
                            int* __restrict__ cur, int n) {
    __shared__ int sh[1024];
    __shared__ int sc;
    int tid = threadIdx.x;
    if (tid == 0) sc = 0;
    __syncthreads();
    for (int base = 0; base < n; base += 1024) {
        int i = base + tid;
        int v = (i < n) ? cnt[i] : 0;
        sh[tid] = v;
        __syncthreads();
#pragma unroll
        for (int d = 1; d < 1024; d <<= 1) {
            int t = (tid >= d) ? sh[tid - d] : 0;
            __syncthreads();
            sh[tid] += t;
            __syncthreads();
        }
        int incl = sh[tid];
        int excl = incl - v + sc;
        if (i < n) { off[i] = excl; cur[i] = excl; }
        __syncthreads();
        if (tid == 1023) sc += incl;
        __syncthreads();
    }
    if (tid == 0) off[n] = sc;
}

__global__ void scatter_kernel(const int* __restrict__ src, const int* __restrict__ dst,
                               int E, int* __restrict__ cur, int* __restrict__ csrc) {
    int i = blockIdx.x * blockDim.x + threadIdx.x;
    if (i < E) {
        int pos = atomicAdd(&cur[dst[i]], 1);
        csrc[pos] = src[i];
    }
}

// ---------------- CSR aggregation: warp per dst node, no atomics ----------------
// agg[n] = (1/max(deg,1)) * sum_{s in nbrs(n)} leaky(hq[n] + hk[s])
__global__ void agg_csr(const int* __restrict__ off, const int* __restrict__ csrc,
                        const float* __restrict__ hq, const float* __restrict__ hk,
                        float* __restrict__ agg, int N) {
    int warp = (blockIdx.x * blockDim.x + threadIdx.x) >> 5;
    int lane = threadIdx.x & 31;
    if (warp >= N) return;
    int b = __ldg(&off[warp]);
    int e = __ldg(&off[warp + 1]);
    float4 q = __ldg(((const float4*)hq) + (size_t)warp * 32 + lane);
    float4 acc = make_float4(0.f, 0.f, 0.f, 0.f);
    for (int base = b; base < e; base += 32) {
        int s = (base + lane < e) ? __ldg(&csrc[base + lane]) : 0;
        int m = min(32, e - base);
        for (int j = 0; j < m; j++) {
            int sj = __shfl_sync(0xffffffffu, s, j);
            float4 k = __ldg(((const float4*)hk) + (size_t)sj * 32 + lane);
            acc.x += leakyf(q.x + k.x);
            acc.y += leakyf(q.y + k.y);
            acc.z += leakyf(q.z + k.z);
            acc.w += leakyf(q.w + k.w);
        }
    }
    float inv = 1.f / (float)max(e - b, 1);
    ((float4*)agg)[(size_t)warp * 32 + lane] =
        make_float4(acc.x * inv, acc.y * inv, acc.z * inv, acc.w * inv);
}

// ---------------- pack weights: bf16 hi/lo images, layout [n][k] (transposed) ----------------
__global__ void pack_w(const float* __restrict__ Wq, const float* __restrict__ Wk,
                       const float* __restrict__ Wr, const float* __restrict__ Wro) {
    int mat = blockIdx.x;  // 0..8
    const float* W;
    switch (mat) {
        case 0: W = Wq;         break;
        case 1: W = Wk;         break;
        case 2: W = Wr;         break;
        case 3: W = Wq + 16384; break;
        case 4: W = Wk + 16384; break;
        case 5: W = Wr + 16384; break;
        default: W = Wro + (mat - 6) * 16384; break;
    }
    unsigned short* hi = (unsigned short*)(g_wpack + (size_t)mat * 16384);
    unsigned short* lo = (unsigned short*)(g_wpack + (size_t)mat * 16384 + 8192);
    int n = threadIdx.x;  // 0..127
    for (int k = 0; k < 128; k++) {
        float w = __ldg(&W[k * 128 + n]);
        __nv_bfloat16 h = __float2bfloat16(w);
        float l = w - __bfloat162float(h);
        __nv_bfloat16 e = __float2bfloat16(l);
        hi[n * 128 + k] = __bfloat16_as_ushort(h);
        lo[n * 128 + k] = __bfloat16_as_ushort(e);
    }
}

// ---------------- GEMM building blocks (256 threads/CTA) ----------------
static __device__ __forceinline__ void conv_A(char* sm, const float* __restrict__ A,
                                              int row0, int N) {
#pragma unroll
    for (int it = 0; it < 16; it++) {
        int idx = it * 256 + threadIdx.x;   // 0..4095
        int r  = idx >> 5;
        int c4 = idx & 31;
        int gidx = row0 + r;
        int gc = gidx < N ? gidx : N - 1;
        float4 v = __ldg(((const float4*)(A + (size_t)gc * 128)) + c4);
        float hx = __bfloat162float(__float2bfloat16(v.x));
        float hy = __bfloat162float(__float2bfloat16(v.y));
        float hz = __bfloat162float(__float2bfloat16(v.z));
        float hw = __bfloat162float(__float2bfloat16(v.w));
        uint2 hiP = make_uint2(pack_bf2(v.x, v.y), pack_bf2(v.z, v.w));
        uint2 loP = make_uint2(pack_bf2(v.x - hx, v.y - hy), pack_bf2(v.z - hz, v.w - hw));
        *(uint2*)(sm + AH_OFF + r * ROWB + c4 * 8) = hiP;
        *(uint2*)(sm + AL_OFF + r * ROWB + c4 * 8) = loP;
    }
}

static __device__ __forceinline__ void copy_B(char* sm, int widx) {
    const uint4* src = (const uint4*)(g_wpack + (size_t)widx * 16384);
#pragma unroll
    for (int it = 0; it < 8; it++) {
        int i = it * 256 + threadIdx.x;   // 0..2047
        int r = i >> 4, c = i & 15;
        *(uint4*)(sm + BH_OFF + r * ROWB + c * 16) = __ldg(src + i);
        *(uint4*)(sm + BL_OFF + r * ROWB + c * 16) = __ldg(src + 2048 + i);
    }
}

static __device__ __forceinline__ void mma_bf16(float* c, uint32_t a0, uint32_t a1,
                                                uint32_t a2, uint32_t a3,
                                                uint32_t b0, uint32_t b1) {
    asm volatile("mma.sync.aligned.m16n8k16.row.col.f32.bf16.bf16.f32 "
                 "{%0,%1,%2,%3}, {%4,%5,%6,%7}, {%8,%9}, {%0,%1,%2,%3};"
                 : "+f"(c[0]), "+f"(c[1]), "+f"(c[2]), "+f"(c[3])
                 : "r"(a0), "r"(a1), "r"(a2), "r"(a3), "r"(b0), "r"(b1));
}

// warp tile 32(M) x 64(N); 3 split segments: Ah*Wh + Al*Wh + Ah*Wl
static __device__ __forceinline__ void run_mma(float acc[2][8][4], const char* sm,
                                               int mbase, int nbase, int g, int t) {
#pragma unroll
    for (int s = 0; s < 3; s++) {
        const char* Ab = sm + (s == 1 ? AL_OFF : AH_OFF) + (mbase + g) * ROWB + t * 4;
        const char* Bb = sm + (s == 2 ? BL_OFF : BH_OFF) + (nbase + g) * ROWB + t * 4;
#pragma unroll
        for (int ks = 0; ks < 8; ks++) {
            int kb = ks * 32;
            uint32_t b[8][2];
#pragma unroll
            for (int nf = 0; nf < 8; nf++) {
                b[nf][0] = *(const uint32_t*)(Bb + nf * (8 * ROWB) + kb);
                b[nf][1] = *(const uint32_t*)(Bb + nf * (8 * ROWB) + kb + 16);
            }
#pragma unroll
            for (int mf = 0; mf < 2; mf++) {
                const char* ap = Ab + mf * (16 * ROWB) + kb;
                uint32_t a0 = *(const uint32_t*)ap;
                uint32_t a1 = *(const uint32_t*)(ap + 8 * ROWB);
                uint32_t a2 = *(const uint32_t*)(ap + 16);
                uint32_t a3 = *(const uint32_t*)(ap + 8 * ROWB + 16);
#pragma unroll
                for (int nf = 0; nf < 8; nf++)
                    mma_bf16(acc[mf][nf], a0, a1, a2, a3, b[nf][0], b[nf][1]);
            }
        }
    }
}

static __device__ __forceinline__ void zero_acc(float acc[2][8][4]) {
#pragma unroll
    for (int mf = 0; mf < 2; mf++)
#pragma unroll
        for (int nf = 0; nf < 8; nf++)
#pragma unroll
            for (int i = 0; i < 4; i++) acc[mf][nf][i] = 0.f;
}

static __device__ __forceinline__ void epi(float acc[2][8][4], float* __restrict__ out,
                                           int row0, int mbase, int nbase, int g, int t,
                                           const float* b0, const float* b1, const float* b2,
                                           int N, int doLeaky) {
    float bias[8][2];
#pragma unroll
    for (int nf = 0; nf < 8; nf++) {
#pragma unroll
        for (int i = 0; i < 2; i++) {
            int col = nbase + nf * 8 + t * 2 + i;
            float bb = __ldg(&b0[col]);
            if (b1) bb += __ldg(&b1[col]);
            if (b2) bb += __ldg(&b2[col]);
            bias[nf][i] = bb;
        }
    }
#pragma unroll
    for (int mf = 0; mf < 2; mf++) {
#pragma unroll
        for (int half = 0; half < 2; half++) {
            int row = row0 + mbase + mf * 16 + g + half * 8;
            if (row < N) {
                float* op = out + (size_t)row * 128;
#pragma unroll
                for (int nf = 0; nf < 8; nf++) {
                    float x = acc[mf][nf][half * 2 + 0] + bias[nf][0];
                    float y = acc[mf][nf][half * 2 + 1] + bias[nf][1];
                    if (doLeaky) { x = leakyf(x); y = leakyf(y); }
                    *(float2*)(op + nbase + nf * 8 + t * 2) = make_float2(x, y);
                }
            }
        }
    }
}

// ---------------- fused Q/K GEMM: hq = A@Wq + bq ; hk = A@Wk + bk ----------------
__global__ void __launch_bounds__(256, 1)
gemm_qk(const float* __restrict__ A, int wq, int wk,
        const float* __restrict__ bq, const float* __restrict__ bk,
        float* __restrict__ hq, float* __restrict__ hk, int N) {
    extern __shared__ char sm[];
    int tid = threadIdx.x, w = tid >> 5, lane = tid & 31;
    int g = lane >> 2, t = lane & 3;
    int mbase = (w >> 1) * 32, nbase = (w & 1) * 64;
    int row0 = blockIdx.x * 128;

    conv_A(sm, A, row0, N);
    copy_B(sm, wq);
    __syncthreads();

    float acc[2][8][4];
    zero_acc(acc);
    run_mma(acc, sm, mbase, nbase, g, t);
    epi(acc, hq, row0, mbase, nbase, g, t, bq, nullptr, nullptr, N, 0);

    __syncthreads();
    copy_B(sm, wk);
    __syncthreads();

    zero_acc(acc);
    run_mma(acc, sm, mbase, nbase, g, t);
    epi(acc, hk, row0, mbase, nbase, g, t, bk, nullptr, nullptr, N, 0);
}

// ---------------- multi-stage accumulating GEMM ----------------
// out = act( sum_s A_s @ W_s + sum_s b_s )
__global__ void __launch_bounds__(256, 1)
gemm_multi(const float* __restrict__ a0, const float* __restrict__ a1, const float* __restrict__ a2,
           int w0, int w1, int w2,
           const float* __restrict__ b0, const float* __restrict__ b1, const float* __restrict__ b2,
           float* __restrict__ out, int N, int nst, int doLeaky) {
    extern __shared__ char sm[];
    int tid = threadIdx.x, w = tid >> 5, lane = tid & 31;
    int g = lane >> 2, t = lane & 3;
    int mbase = (w >> 1) * 32, nbase = (w & 1) * 64;
    int row0 = blockIdx.x * 128;

    const float* As[3] = {a0, a1, a2};
    int ws[3] = {w0, w1, w2};

    float acc[2][8][4];
    zero_acc(acc);

    for (int s = 0; s < nst; s++) {
        if (s) __syncthreads();
        conv_A(sm, As[s], row0, N);
        copy_B(sm, ws[s]);
        __syncthreads();
        run_mma(acc, sm, mbase, nbase, g, t);
    }

    epi(acc, out, row0, mbase, nbase, g, t, b0, b1, b2, N, doLeaky);
}

// ---------------- launch ----------------
extern "C" void kernel_launch(void* const* d_in, const int* in_sizes, int n_in,
                              void* d_out, int out_size) {
    const float* feats = (const float*)d_in[0];
    const float* Wq    = (const float*)d_in[1];
    const float* bq    = (const float*)d_in[2];
    const float* Wk    = (const float*)d_in[3];
    const float* bk    = (const float*)d_in[4];
    const float* Wr    = (const float*)d_in[5];
    const float* br    = (const float*)d_in[6];
    const float* Wro   = (const float*)d_in[7];
    const float* bro   = (const float*)d_in[8];
    const int*   src   = (const int*)d_in[9];
    const int*   dst   = (const int*)d_in[10];

    int N = in_sizes[0] / DIM;   // 50000
    int E = in_sizes[9];         // 800000
    float* out = (float*)d_out;

    float *hq, *hk, *agg, *h1, *h2;
    int *cnt, *off, *cur, *csrc;
    cudaGetSymbolAddress((void**)&hq,   g_hq);
    cudaGetSymbolAddress((void**)&hk,   g_hk);
    cudaGetSymbolAddress((void**)&agg,  g_agg);
    cudaGetSymbolAddress((void**)&h1,   g_h1);
    cudaGetSymbolAddress((void**)&h2,   g_h2);
    cudaGetSymbolAddress((void**)&cnt,  g_cnt);
    cudaGetSymbolAddress((void**)&off,  g_off);
    cudaGetSymbolAddress((void**)&cur,  g_cur);
    cudaGetSymbolAddress((void**)&csrc, g_csrc);

    cudaFuncSetAttribute(gemm_qk,    cudaFuncAttributeMaxDynamicSharedMemorySize, SMEM_TOTAL);
    cudaFuncSetAttribute(gemm_multi, cudaFuncAttributeMaxDynamicSharedMemorySize, SMEM_TOTAL);

    int gM = (N + 127) / 128;    // 391
    int gAgg = (N * 32 + 255) / 256;

    // weight packing (independent of CSR build)
    pack_w<<<9, 128>>>(Wq, Wk, Wr, Wro);

    // CSR build (by dst)
    zero_int<<<(N + 255) / 256, 256>>>(cnt, N);
    cnt_kernel<<<(E + 255) / 256, 256>>>(dst, E, cnt);
    scan_kernel<<<1, 1024>>>(cnt, off, cur, N);
    scatter_kernel<<<(E + 255) / 256, 256>>>(src, dst, E, cur, csrc);

    // ---- layer 0 ----
    gemm_qk<<<gM, 256, SMEM_TOTAL>>>(feats, 0, 1, bq, bk, hq, hk, N);
    agg_csr<<<gAgg, 256>>>(off, csrc, hq, hk, agg, N);
    gemm_multi<<<gM, 256, SMEM_TOTAL>>>(agg, nullptr, nullptr, 2, -1, -1,
                                        br, nullptr, nullptr, h1, N, 1, 1);

    // ---- layer 1 ----
    gemm_qk<<<gM, 256, SMEM_TOTAL>>>(h1, 3, 4, bq + 128, bk + 128, hq, hk, N);
    agg_csr<<<gAgg, 256>>>(off, csrc, hq, hk, agg, N);
    gemm_multi<<<gM, 256, SMEM_TOTAL>>>(agg, nullptr, nullptr, 5, -1, -1,
                                        br + 128, nullptr, nullptr, h2, N, 1, 1);

    // ---- jumping-knowledge readout (3 stages accumulated in registers) ----
    gemm_multi<<<gM, 256, SMEM_TOTAL>>>(feats, h1, h2, 6, 7, 8,
                                        bro, bro + 128, bro + 256, out, N, 3, 0);
}